// round 4
// baseline (speedup 1.0000x reference)
#include <cuda_runtime.h>
#include <cuda.h>
#include <cstdint>

// Problem constants
#define TT    9
#define BB    8
#define CC    256
#define HWHW  3136
#define PIX   8
#define NTHREADS 512
#define NT    7
#define CHUNKS_PER_B 56
#define NBLOCKS 448

#define TMA_T 5                            // t = 0..4 via TMA
#define CP_T0 5                            // t = 5..8 via cp.async
#define TMA_BYTES (TMA_T*CC*PIX*4)         // 40960

#define TILE_FLOATS (TT*CC*PIX)            // 18432 floats = 73728 B

// SMEM layout (float offsets)
#define OFF_BUF0  0
#define OFF_BUF1  (TILE_FLOATS)
#define OFF_WC    (2*TILE_FLOATS)
#define OFF_WO    (OFF_WC + CC)
#define OFF_PART  (OFF_WO + CC)            // [16 warps][80]
#define OFF_SCOR  (OFF_PART + 16*80)       // [80]
#define OFF_MBAR  (OFF_SCOR + 80)          // 2 x u64 (8B aligned)
#define SMEM_FLOATS (OFF_MBAR + 4)
#define SMEM_BYTES  (SMEM_FLOATS * 4)

// ---------------- PTX helpers ----------------
#define MBAR_INIT(addr, cnt) \
    asm volatile("mbarrier.init.shared.b64 [%0], %1;" :: "r"(addr), "r"(cnt) : "memory")
#define MBAR_EXPECT_TX(addr, bytes) \
    asm volatile("mbarrier.arrive.expect_tx.shared.b64 _, [%0], %1;" :: "r"(addr), "r"(bytes) : "memory")
#define MBAR_WAIT(addr, parity) do {                                           \
    asm volatile("{\n\t.reg .pred P;\n\t"                                      \
        "WL_%=:\n\t"                                                           \
        "mbarrier.try_wait.parity.acquire.cta.shared::cta.b64 P, [%0], %1, 0x989680;\n\t" \
        "@P bra WD_%=;\n\t"                                                    \
        "bra WL_%=;\n\t"                                                       \
        "WD_%=:\n\t}"                                                          \
        :: "r"(addr), "r"(parity) : "memory");                                 \
} while (0)

__device__ __forceinline__ void tma_load_tile(uint32_t dst, const CUtensorMap* map,
                                              int x, int z, uint32_t mbar)
{
    asm volatile(
        "cp.async.bulk.tensor.4d.shared::cta.global.tile.mbarrier::complete_tx::bytes "
        "[%0], [%1, {%2, %3, %4, %5}], [%6];"
        :: "r"(dst), "l"(map), "r"(x), "r"(0), "r"(z), "r"(0), "r"(mbar)
        : "memory");
}

// cp.async slice loader: t = 5..8, thread -> (c = tid>>1, q = tid&1)
__device__ __forceinline__ void cp_issue(uint32_t buf_bytes,
                                         const float* __restrict__ src, int tid)
{
    const int q = tid & 1;
    const int c = tid >> 1;
    const float* g = src + (size_t)(CP_T0) * BB * CC * HWHW + (size_t)c * HWHW + q * 4;
    uint32_t s = buf_bytes + (uint32_t)(((CP_T0 * CC + c) * PIX + q * 4) * 4);
    #pragma unroll
    for (int j = 0; j < TT - CP_T0; ++j) {
        asm volatile("cp.async.cg.shared.global [%0], [%1], 16;\n"
                     :: "r"(s), "l"(g) : "memory");
        g += (size_t)BB * CC * HWHW;
        s += CC * PIX * 4;
    }
    asm volatile("cp.async.commit_group;\n" ::: "memory");
}

// ---------------- hybrid TMA + cp.async kernel ----------------
__global__ __launch_bounds__(NTHREADS, 1)
void tfma_hyb_kernel(const __grid_constant__ CUtensorMap tmap,
                     const float* __restrict__ seq,
                     const float* __restrict__ wptr,
                     const float* __restrict__ bptr,
                     const float* __restrict__ gptr,
                     float* __restrict__ out)
{
    extern __shared__ float sm[];
    float* wc   = sm + OFF_WC;
    float* wo   = sm + OFF_WO;
    float* part = sm + OFF_PART;
    float* scor = sm + OFF_SCOR;
    const uint32_t smem_base = (uint32_t)__cvta_generic_to_shared(sm);
    const uint32_t mbar0 = smem_base + OFF_MBAR * 4;
    const uint32_t mbar1 = mbar0 + 8;

    const int tid   = threadIdx.x;
    const int lane  = tid & 31;
    const int wrp   = tid >> 5;
    const int p     = tid & (PIX - 1);
    const int cg    = tid >> 3;                 // 0..63
    const int bidx  = blockIdx.x / CHUNKS_PER_B;
    const int chunk = blockIdx.x % CHUNKS_PER_B;
    const int pixbase = chunk * NT * PIX;

    const float* sbase = seq + (size_t)bidx * CC * HWHW;  // + pix for cp.async

    if (tid < CC) {
        wc[tid] = wptr[tid];
        wo[tid] = wptr[CC + tid];
    }
    if (tid == 0) {
        MBAR_INIT(mbar0, 1);
        MBAR_INIT(mbar1, 1);
    }
    __syncthreads();

    // prologue: tiles 0 and 1
    if (tid == 0) {
        MBAR_EXPECT_TX(mbar0, TMA_BYTES);
        tma_load_tile(smem_base + OFF_BUF0 * 4, &tmap, pixbase, bidx, mbar0);
        MBAR_EXPECT_TX(mbar1, TMA_BYTES);
        tma_load_tile(smem_base + OFF_BUF1 * 4, &tmap, pixbase + PIX, bidx, mbar1);
    }
    cp_issue(smem_base + OFF_BUF0 * 4, sbase + pixbase, tid);
    cp_issue(smem_base + OFF_BUF1 * 4, sbase + pixbase + PIX, tid);

    const float bv    = bptr[0];
    const float gamma = gptr[0];
    float* obase0 = out + (size_t)bidx * CC * HWHW;

    #pragma unroll 1
    for (int k = 0; k < NT; ++k) {
        // ---- wait for tile k (own cp.async groups + TMA mbar), then barrier
        if (k == NT - 1)
            asm volatile("cp.async.wait_group 0;\n" ::: "memory");
        else
            asm volatile("cp.async.wait_group 1;\n" ::: "memory");
        MBAR_WAIT((k & 1) ? mbar1 : mbar0, (k >> 1) & 1);
        __syncthreads();      // peer cp.async data visibility

        const float* tile = sm + ((k & 1) ? OFF_BUF1 : OFF_BUF0);
        const int pix0 = pixbase + k * PIX;

        // ---- phase 2: pull slice to registers, score partials ----
        float rv[4][TT];
        float acc[TT];
        float accc = 0.f;
        #pragma unroll
        for (int t = 0; t < TT; ++t) acc[t] = 0.f;

        #pragma unroll
        for (int ci = 0; ci < 4; ++ci) {
            const int c  = cg + (ci << 6);
            const float wot = wo[c];
            const float wct = wc[c];
            #pragma unroll
            for (int t = 0; t < TT; ++t) {
                rv[ci][t] = tile[(t * CC + c) * PIX + p];
                acc[t] = fmaf(rv[ci][t], wot, acc[t]);
                if (t == TT / 2) accc = fmaf(rv[ci][t], wct, accc);
            }
        }
        #pragma unroll
        for (int t = 0; t < TT; ++t) {
            acc[t] += __shfl_xor_sync(0xffffffffu, acc[t], 8);
            acc[t] += __shfl_xor_sync(0xffffffffu, acc[t], 16);
        }
        accc += __shfl_xor_sync(0xffffffffu, accc, 8);
        accc += __shfl_xor_sync(0xffffffffu, accc, 16);
        if (lane < PIX) {
            #pragma unroll
            for (int t = 0; t < TT; ++t)
                part[wrp * 80 + t * PIX + lane] = acc[t];
            part[wrp * 80 + TT * PIX + lane] = accc;
        }
        __syncthreads();      // partials ready; tile k fully consumed

        // ---- issue tile k+2 into buf(k&1) (both engines) ----
        if (k + 2 < NT) {
            if (tid == 0) {
                const uint32_t mb  = (k & 1) ? mbar1 : mbar0;
                const uint32_t dst = smem_base + ((k & 1) ? OFF_BUF1 : OFF_BUF0) * 4;
                MBAR_EXPECT_TX(mb, TMA_BYTES);
                tma_load_tile(dst, &tmap, pixbase + (k + 2) * PIX, bidx, mb);
            }
            cp_issue(smem_base + ((k & 1) ? OFF_BUF1 : OFF_BUF0) * 4,
                     sbase + pixbase + (k + 2) * PIX, tid);
        }

        // ---- cross-warp reduce ----
        if (tid < 80) {
            float s = 0.f;
            #pragma unroll
            for (int g = 0; g < 16; ++g) s += part[g * 80 + tid];
            scor[tid] = s;
        }
        __syncthreads();

        // ---- phase 3: softmax + attended sum from registers ----
        {
            const float centv = scor[TT * PIX + p];
            float a[TT];
            float m = -1e30f;
            #pragma unroll
            for (int t = 0; t < TT; ++t) {
                a[t] = scor[t * PIX + p] + centv + bv;
                m = fmaxf(m, a[t]);
            }
            float sum = 0.f;
            #pragma unroll
            for (int t = 0; t < TT; ++t) {
                a[t] = __expf(a[t] - m);
                sum += a[t];
            }
            const float inv = 1.f / sum;
            #pragma unroll
            for (int t = 0; t < TT; ++t) a[t] *= inv;

            float* ob = obase0 + pix0 + p;
            #pragma unroll
            for (int ci = 0; ci < 4; ++ci) {
                const int c = cg + (ci << 6);
                float s = 0.f;
                #pragma unroll
                for (int t = 0; t < TT; ++t)
                    s = fmaf(a[t], rv[ci][t], s);
                ob[(size_t)c * HWHW] = rv[ci][TT / 2] + gamma * s;
            }
        }
        // no trailing barrier: next iteration gates on waits + barrier
    }
}

// ---------------- fallback kernel (proven cp.async-only path) ----------------
__device__ __forceinline__ void fb_issue_tile(uint32_t smem_dst_bytes,
                                              const float* __restrict__ src, int tid)
{
    const int q = tid & 1;
    const int c = tid >> 1;
    const float* g = src + (size_t)c * HWHW + q * 4;
    uint32_t s = smem_dst_bytes + (uint32_t)((c * PIX + q * 4) * 4);
    #pragma unroll
    for (int t = 0; t < TT; ++t) {
        asm volatile("cp.async.cg.shared.global [%0], [%1], 16;\n"
                     :: "r"(s), "l"(g) : "memory");
        g += (size_t)BB * CC * HWHW;
        s += CC * PIX * 4;
    }
}

__global__ __launch_bounds__(NTHREADS, 1)
void tfma_fb_kernel(const float* __restrict__ seq,
                    const float* __restrict__ wptr,
                    const float* __restrict__ bptr,
                    const float* __restrict__ gptr,
                    float* __restrict__ out)
{
    extern __shared__ float sm[];
    float* wc   = sm + OFF_WC;
    float* wo   = sm + OFF_WO;
    float* part = sm + OFF_PART;
    float* scor = sm + OFF_SCOR;
    const uint32_t smem_base = (uint32_t)__cvta_generic_to_shared(sm);

    const int tid   = threadIdx.x;
    const int lane  = tid & 31;
    const int wrp   = tid >> 5;
    const int p     = tid & (PIX - 1);
    const int cg    = tid >> 3;
    const int bidx  = blockIdx.x / CHUNKS_PER_B;
    const int chunk = blockIdx.x % CHUNKS_PER_B;
    const float* tbase = seq + (size_t)bidx * CC * HWHW;

    if (tid < CC) { wc[tid] = wptr[tid]; wo[tid] = wptr[CC + tid]; }

    fb_issue_tile(smem_base + OFF_BUF0 * 4, tbase + (size_t)(chunk * NT) * PIX, tid);
    asm volatile("cp.async.commit_group;\n" ::: "memory");

    const float bv    = bptr[0];
    const float gamma = gptr[0];
    float* obase0 = out + (size_t)bidx * CC * HWHW;

    for (int k = 0; k < NT; ++k) {
        if (k + 1 < NT)
            fb_issue_tile(smem_base + ((k & 1) ? OFF_BUF0 : OFF_BUF1) * 4,
                          tbase + (size_t)((chunk * NT + k + 1) * PIX), tid);
        asm volatile("cp.async.commit_group;\n" ::: "memory");
        asm volatile("cp.async.wait_group 1;\n" ::: "memory");
        __syncthreads();

        const float* tile = sm + ((k & 1) ? OFF_BUF1 : OFF_BUF0);
        const int pix0 = (chunk * NT + k) * PIX;

        float rv[4][TT];
        float acc[TT]; float accc = 0.f;
        #pragma unroll
        for (int t = 0; t < TT; ++t) acc[t] = 0.f;
        #pragma unroll
        for (int ci = 0; ci < 4; ++ci) {
            const int c = cg + (ci << 6);
            const float wot = wo[c], wct = wc[c];
            #pragma unroll
            for (int t = 0; t < TT; ++t) {
                rv[ci][t] = tile[(t * CC + c) * PIX + p];
                acc[t] = fmaf(rv[ci][t], wot, acc[t]);
                if (t == TT / 2) accc = fmaf(rv[ci][t], wct, accc);
            }
        }
        #pragma unroll
        for (int t = 0; t < TT; ++t) {
            acc[t] += __shfl_xor_sync(0xffffffffu, acc[t], 8);
            acc[t] += __shfl_xor_sync(0xffffffffu, acc[t], 16);
        }
        accc += __shfl_xor_sync(0xffffffffu, accc, 8);
        accc += __shfl_xor_sync(0xffffffffu, accc, 16);
        if (lane < PIX) {
            #pragma unroll
            for (int t = 0; t < TT; ++t) part[wrp * 80 + t * PIX + lane] = acc[t];
            part[wrp * 80 + TT * PIX + lane] = accc;
        }
        __syncthreads();
        if (tid < 80) {
            float s = 0.f;
            #pragma unroll
            for (int g = 0; g < 16; ++g) s += part[g * 80 + tid];
            scor[tid] = s;
        }
        __syncthreads();
        {
            const float centv = scor[TT * PIX + p];
            float a[TT]; float m = -1e30f;
            #pragma unroll
            for (int t = 0; t < TT; ++t) { a[t] = scor[t * PIX + p] + centv + bv; m = fmaxf(m, a[t]); }
            float sum = 0.f;
            #pragma unroll
            for (int t = 0; t < TT; ++t) { a[t] = __expf(a[t] - m); sum += a[t]; }
            const float inv = 1.f / sum;
            #pragma unroll
            for (int t = 0; t < TT; ++t) a[t] *= inv;

            float* ob = obase0 + pix0 + p;
            #pragma unroll
            for (int ci = 0; ci < 4; ++ci) {
                const int c = cg + (ci << 6);
                float s = 0.f;
                #pragma unroll
                for (int t = 0; t < TT; ++t) s = fmaf(a[t], rv[ci][t], s);
                ob[(size_t)c * HWHW] = rv[ci][TT / 2] + gamma * s;
            }
        }
        __syncthreads();
    }
}

// ---------------- host ----------------
typedef CUresult (*EncodeTiledFn)(CUtensorMap*, CUtensorMapDataType, cuuint32_t, void*,
                                  const cuuint64_t*, const cuuint64_t*,
                                  const cuuint32_t*, const cuuint32_t*,
                                  CUtensorMapInterleave, CUtensorMapSwizzle,
                                  CUtensorMapL2promotion, CUtensorMapFloatOOBfill);

extern "C" void kernel_launch(void* const* d_in, const int* in_sizes, int n_in,
                              void* d_out, int out_size)
{
    (void)in_sizes; (void)n_in; (void)out_size;
    const float* seq   = (const float*)d_in[0];
    const float* w     = (const float*)d_in[1];
    const float* bv    = (const float*)d_in[2];
    const float* gamma = (const float*)d_in[3];
    float* out = (float*)d_out;

    void* fn = nullptr;
    cudaDriverEntryPointQueryResult qr = cudaDriverEntryPointSymbolNotFound;
    cudaGetDriverEntryPointByVersion("cuTensorMapEncodeTiled", &fn, 12000,
                                     cudaEnableDefault, &qr);

    bool tma_ok = false;
    CUtensorMap tmap;
    if (fn && qr == cudaDriverEntryPointSuccess) {
        cuuint64_t dims[4]    = {HWHW, CC, BB, TT};
        cuuint64_t strides[3] = {(cuuint64_t)HWHW * 4,
                                 (cuuint64_t)CC * HWHW * 4,
                                 (cuuint64_t)BB * CC * HWHW * 4};
        cuuint32_t box[4]     = {PIX, CC, 1, TMA_T};   // t = 0..4 only
        cuuint32_t estr[4]    = {1, 1, 1, 1};
        CUresult r = ((EncodeTiledFn)fn)(
            &tmap, CU_TENSOR_MAP_DATA_TYPE_FLOAT32, 4, (void*)seq,
            dims, strides, box, estr,
            CU_TENSOR_MAP_INTERLEAVE_NONE, CU_TENSOR_MAP_SWIZZLE_NONE,
            CU_TENSOR_MAP_L2_PROMOTION_L2_128B, CU_TENSOR_MAP_FLOAT_OOB_FILL_NONE);
        tma_ok = (r == CUDA_SUCCESS);
    }

    if (tma_ok) {
        cudaFuncSetAttribute(tfma_hyb_kernel,
                             cudaFuncAttributeMaxDynamicSharedMemorySize, SMEM_BYTES);
        tfma_hyb_kernel<<<NBLOCKS, NTHREADS, SMEM_BYTES>>>(tmap, seq, w, bv, gamma, out);
    } else {
        cudaFuncSetAttribute(tfma_fb_kernel,
                             cudaFuncAttributeMaxDynamicSharedMemorySize, SMEM_BYTES);
        tfma_fb_kernel<<<NBLOCKS, NTHREADS, SMEM_BYTES>>>(seq, w, bv, gamma, out);
    }
}